// round 2
// baseline (speedup 1.0000x reference)
#include <cuda_runtime.h>
#include <math.h>

// ---------------- problem dims ----------------
#define S_DIM 4096
#define B_DIM 2
#define E_DIM 1024
#define H_DIM 8
#define R_DIM 2
#define C_DIM 64
#define D_DIM 128
#define NC_DIM 64                    // S / C
#define NSEG (B_DIM*R_DIM*H_DIM)     // 32
#define MROWS (S_DIM*B_DIM)          // 8192
#define SCALE_F 0.08838834764831845f // D^-0.5
#define NEG_F (-1e9f)
#define NEG_SELF_F (-1e5f)

// ---------------- scratch (device globals; no allocation) ----------------
__device__ float g_qraw[MROWS*E_DIM];     // x@wq^T + bq
__device__ float g_k[MROWS*E_DIM];        // qraw / ||qraw||_E
__device__ float g_v[MROWS*E_DIM];        // x@wv^T + bv
__device__ float g_ocomb[MROWS*E_DIM];    // combined heads, [S,B,E]
__device__ float g_oout[NSEG*S_DIM*D_DIM];// per-(b,r,h) outputs, original token order
__device__ float g_olse[NSEG*S_DIM];      // per-(b,r,h) lse, original token order
__device__ int   g_hash[NSEG*S_DIM];
__device__ int   g_sidx[NSEG*S_DIM];      // sorted token ids
__device__ int   g_shash[NSEG*S_DIM];     // sorted hash values

// ---------------- GEMM: C[M,N] = A[M,K] @ W[N,K]^T + bias[N] ----------------
// BM=128, BN=64, BK=16, 256 threads, 8x4 per-thread micro-tile.
__global__ void gemm_bias_kernel(const float* __restrict__ A,
                                 const float* __restrict__ W,
                                 const float* __restrict__ bias,
                                 float* __restrict__ C,
                                 int M, int N, int K)
{
    __shared__ float As[16][132];  // [k][m], padded
    __shared__ float Ws[16][68];   // [k][n], padded

    const int tid = threadIdx.x;
    const int bm = blockIdx.y * 128;
    const int bn = blockIdx.x * 64;
    const int tm = tid >> 4;   // 0..15 -> rows tm*8..tm*8+7
    const int tn = tid & 15;   // 0..15 -> cols tn*4..tn*4+3

    float acc[8][4];
#pragma unroll
    for (int i = 0; i < 8; i++)
#pragma unroll
        for (int j = 0; j < 4; j++) acc[i][j] = 0.f;

    for (int k0 = 0; k0 < K; k0 += 16) {
        // A tile: 128x16 = 512 float4, 2 per thread
#pragma unroll
        for (int it = 0; it < 2; it++) {
            int l = it * 256 + tid;
            int m = l >> 2, kq = (l & 3) * 4;
            float4 va = *(const float4*)&A[(size_t)(bm + m) * K + k0 + kq];
            As[kq + 0][m] = va.x; As[kq + 1][m] = va.y;
            As[kq + 2][m] = va.z; As[kq + 3][m] = va.w;
        }
        // W tile: 64x16 = 256 float4, 1 per thread
        {
            int n = tid >> 2, kq = (tid & 3) * 4;
            float4 vw = *(const float4*)&W[(size_t)(bn + n) * K + k0 + kq];
            Ws[kq + 0][n] = vw.x; Ws[kq + 1][n] = vw.y;
            Ws[kq + 2][n] = vw.z; Ws[kq + 3][n] = vw.w;
        }
        __syncthreads();

#pragma unroll
        for (int k = 0; k < 16; k++) {
            float4 a0 = *(const float4*)&As[k][tm * 8];
            float4 a1 = *(const float4*)&As[k][tm * 8 + 4];
            float4 b0 = *(const float4*)&Ws[k][tn * 4];
            float av[8] = {a0.x, a0.y, a0.z, a0.w, a1.x, a1.y, a1.z, a1.w};
            float bv[4] = {b0.x, b0.y, b0.z, b0.w};
#pragma unroll
            for (int i = 0; i < 8; i++)
#pragma unroll
                for (int j = 0; j < 4; j++) acc[i][j] += av[i] * bv[j];
        }
        __syncthreads();
    }

    float4 bb = *(const float4*)&bias[bn + tn * 4];
#pragma unroll
    for (int i = 0; i < 8; i++) {
        float4 o;
        o.x = acc[i][0] + bb.x; o.y = acc[i][1] + bb.y;
        o.z = acc[i][2] + bb.z; o.w = acc[i][3] + bb.w;
        *(float4*)&C[(size_t)(bm + tm * 8 + i) * N + bn + tn * 4] = o;
    }
}

// ---------------- k = q / ||q||  (norm over full E) ----------------
__global__ void norm_kernel()
{
    const int row = blockIdx.x;
    const float* q = g_qraw + (size_t)row * E_DIM;
    float ss = 0.f;
    for (int i = threadIdx.x; i < E_DIM; i += 256) { float v = q[i]; ss += v * v; }
#pragma unroll
    for (int o = 16; o > 0; o >>= 1) ss += __shfl_xor_sync(0xffffffffu, ss, o);
    __shared__ float red[8];
    __shared__ float s_inv;
    if ((threadIdx.x & 31) == 0) red[threadIdx.x >> 5] = ss;
    __syncthreads();
    if (threadIdx.x == 0) {
        float t = 0.f;
#pragma unroll
        for (int i = 0; i < 8; i++) t += red[i];
        s_inv = 1.0f / sqrtf(t);
    }
    __syncthreads();
    const float inv = s_inv;
    for (int i = threadIdx.x; i < E_DIM; i += 256)
        g_k[(size_t)row * E_DIM + i] = q[i] * inv;
}

// ---------------- LSH hashing: argmax over [lin, -lin] ----------------
// grid: (S/256, NSEG). Uses unnormalized q (argmax is scale-invariant
// since k = q * positive per-token scalar).
__global__ void hash_kernel(const float* __restrict__ hash_w)
{
    const int seg = blockIdx.y;              // (b*R + r)*H + h
    const int b = seg / (R_DIM * H_DIM);
    const int r = (seg / H_DIM) % R_DIM;
    const int h = seg % H_DIM;

    __shared__ float hw[D_DIM * 8];          // hash_w[r][h][d][m]
    const float* hwp = hash_w + (size_t)(r * H_DIM + h) * D_DIM * 8;
    for (int i = threadIdx.x; i < D_DIM * 8; i += 256) hw[i] = hwp[i];
    __syncthreads();

    const int s = blockIdx.x * 256 + threadIdx.x;
    const float* qp = g_qraw + ((size_t)s * B_DIM + b) * E_DIM + h * D_DIM;

    float acc[8];
#pragma unroll
    for (int m = 0; m < 8; m++) acc[m] = 0.f;
    for (int d = 0; d < D_DIM; d++) {
        float qv = qp[d];
#pragma unroll
        for (int m = 0; m < 8; m++) acc[m] += qv * hw[d * 8 + m];
    }
    float best = acc[0]; int bi = 0;
#pragma unroll
    for (int m = 1; m < 8; m++) if (acc[m] > best) { best = acc[m]; bi = m; }
#pragma unroll
    for (int m = 0; m < 8; m++) if (-acc[m] > best) { best = -acc[m]; bi = 8 + m; }
    g_hash[(size_t)seg * S_DIM + s] = bi;
}

// ---------------- stable counting sort (16 buckets) ----------------
// one block of 512 threads per segment; each thread owns 8 consecutive tokens.
__global__ void sort_kernel()
{
    const int seg = blockIdx.x;
    const int tid = threadIdx.x;
    __shared__ int tc[512][16];
    __shared__ int base[16], tot[16];

    const int* hp = g_hash + (size_t)seg * S_DIM;
#pragma unroll
    for (int m = 0; m < 16; m++) tc[tid][m] = 0;
    int myh[8];
#pragma unroll
    for (int i = 0; i < 8; i++) {
        myh[i] = hp[tid * 8 + i];
        tc[tid][myh[i]]++;
    }
    __syncthreads();
    if (tid < 16) {
        int run = 0;
        for (int t = 0; t < 512; t++) { int v = tc[t][tid]; tc[t][tid] = run; run += v; }
        tot[tid] = run;
    }
    __syncthreads();
    if (tid == 0) {
        int run = 0;
#pragma unroll
        for (int m = 0; m < 16; m++) { base[m] = run; run += tot[m]; }
    }
    __syncthreads();
#pragma unroll
    for (int i = 0; i < 8; i++) {
        int hh = myh[i];
        int pos = base[hh] + tc[tid][hh];
        tc[tid][hh]++;
        g_sidx[(size_t)seg * S_DIM + pos]  = tid * 8 + i;
        g_shash[(size_t)seg * S_DIM + pos] = hh;
    }
}

// ---------------- chunked LSH attention ----------------
// one block per (seg, chunk). 256 threads.
// NOTE reference-broadcast semantics: mask windows are indexed by the query's
// SLOT c within its chunk (because C == n_c), not by the chunk n. So each
// block needs the whole segment's sorted hash/idx arrays -> staged in shared.
#define QS 132
#define LGS 196
#define ATTN_SMEM ((2*64*QS + 64*LGS) * 4 + 2 * S_DIM * 4)

__global__ void attn_kernel()
{
    extern __shared__ float sm[];
    float* q_sh  = sm;                      // [64][QS]
    float* kv_sh = sm + 64 * QS;            // [64][QS]
    float* lg    = sm + 2 * 64 * QS;        // [64][LGS]
    int* sidx_sh  = (int*)(sm + 2 * 64 * QS + 64 * LGS);  // [4096]
    int* shash_sh = sidx_sh + S_DIM;                       // [4096]

    const int bid = blockIdx.x;
    const int n   = bid % NC_DIM;
    const int seg = bid / NC_DIM;           // (b*R + r)*H + h
    const int b   = seg / (R_DIM * H_DIM);
    const int h   = seg % H_DIM;
    const int tid = threadIdx.x;

    const int* gsidx  = g_sidx  + (size_t)seg * S_DIM;
    const int* gshash = g_shash + (size_t)seg * S_DIM;
    for (int i = tid; i < S_DIM; i += 256) {
        sidx_sh[i]  = gsidx[i];
        shash_sh[i] = gshash[i];
    }
    __syncthreads();

    // load q (scaled)
    for (int idx = tid; idx < 64 * 128; idx += 256) {
        int qi = idx >> 7, d = idx & 127;
        int tok = sidx_sh[n * 64 + qi];
        q_sh[qi * QS + d] =
            SCALE_F * g_qraw[((size_t)tok * B_DIM + b) * E_DIM + h * D_DIM + d];
    }

    // ---- logits: 3 chunks of 64 keys (K window of chunk n) ----
    const int tqi = tid >> 4;   // 0..15 -> queries tqi*4..+3
    const int tj  = tid & 15;   // 0..15 -> keys    tj*4..+3
    for (int c = 0; c < 3; c++) {
        __syncthreads();
        int kchunk = (n + c + NC_DIM - 1) % NC_DIM;
        for (int idx = tid; idx < 64 * 128; idx += 256) {
            int j = idx >> 7, d = idx & 127;
            int tok = sidx_sh[kchunk * 64 + j];
            kv_sh[j * QS + d] =
                g_k[((size_t)tok * B_DIM + b) * E_DIM + h * D_DIM + d];
        }
        __syncthreads();

        float lacc[4][4];
#pragma unroll
        for (int i = 0; i < 4; i++)
#pragma unroll
            for (int j = 0; j < 4; j++) lacc[i][j] = 0.f;

        for (int d4 = 0; d4 < 32; d4++) {
            float4 qv[4], kv4[4];
#pragma unroll
            for (int i = 0; i < 4; i++)
                qv[i] = *(const float4*)&q_sh[(tqi * 4 + i) * QS + d4 * 4];
#pragma unroll
            for (int j = 0; j < 4; j++)
                kv4[j] = *(const float4*)&kv_sh[(tj * 4 + j) * QS + d4 * 4];
#pragma unroll
            for (int i = 0; i < 4; i++)
#pragma unroll
                for (int j = 0; j < 4; j++)
                    lacc[i][j] += qv[i].x * kv4[j].x + qv[i].y * kv4[j].y +
                                  qv[i].z * kv4[j].z + qv[i].w * kv4[j].w;
        }
#pragma unroll
        for (int i = 0; i < 4; i++) {
            int qq = tqi * 4 + i;                    // slot within chunk
            int qpos = n * 64 + qq;                  // sorted position of query
            int qhash = shash_sh[qpos];
            int qtok  = sidx_sh[qpos];
            // MASK window is chunk index == slot qq (reference broadcast artifact)
            int mchunk = (qq + c + NC_DIM - 1) % NC_DIM;
#pragma unroll
            for (int j = 0; j < 4; j++) {
                int jj = tj * 4 + j;
                int mpos = mchunk * 64 + jj;
                float lv = lacc[i][j];
                if (qhash != shash_sh[mpos]) lv = NEG_F;      // different hash
                if (qtok  == sidx_sh[mpos])  lv = NEG_SELF_F; // "self"
                lg[qq * LGS + c * 64 + jj] = lv;
            }
        }
    }
    __syncthreads();

    // ---- softmax + lse per query row ----
    if (tid < 64) {
        float m = -3.402823466e38f;
        for (int j = 0; j < 192; j++) m = fmaxf(m, lg[tid * LGS + j]);
        float ssum = 0.f;
        for (int j = 0; j < 192; j++) {
            float e = expf(lg[tid * LGS + j] - m);
            lg[tid * LGS + j] = e;
            ssum += e;
        }
        float inv = 1.0f / ssum;
        for (int j = 0; j < 192; j++) lg[tid * LGS + j] *= inv;
        g_olse[(size_t)seg * S_DIM + sidx_sh[n * 64 + tid]] = m + logf(ssum);
    }
    __syncthreads();

    // ---- output: o = P @ V, scattered to original token order ----
    const int tq = tid >> 3;   // 0..31 -> queries tq*2, tq*2+1
    const int td = tid & 7;    // 0..7  -> dims td*16..td*16+15
    float oacc0[16], oacc1[16];
#pragma unroll
    for (int u = 0; u < 16; u++) { oacc0[u] = 0.f; oacc1[u] = 0.f; }

    for (int c = 0; c < 3; c++) {
        int kchunk = (n + c + NC_DIM - 1) % NC_DIM;
        for (int idx = tid; idx < 64 * 128; idx += 256) {
            int j = idx >> 7, d = idx & 127;
            int tok = sidx_sh[kchunk * 64 + j];
            kv_sh[j * QS + d] =
                g_v[((size_t)tok * B_DIM + b) * E_DIM + h * D_DIM + d];
        }
        __syncthreads();
        for (int j = 0; j < 64; j++) {
            float p0 = lg[(tq * 2 + 0) * LGS + c * 64 + j];
            float p1 = lg[(tq * 2 + 1) * LGS + c * 64 + j];
            const float* vrow = &kv_sh[j * QS + td * 16];
#pragma unroll
            for (int d4 = 0; d4 < 4; d4++) {
                float4 v4 = *(const float4*)&vrow[d4 * 4];
                oacc0[d4 * 4 + 0] += p0 * v4.x; oacc1[d4 * 4 + 0] += p1 * v4.x;
                oacc0[d4 * 4 + 1] += p0 * v4.y; oacc1[d4 * 4 + 1] += p1 * v4.y;
                oacc0[d4 * 4 + 2] += p0 * v4.z; oacc1[d4 * 4 + 2] += p1 * v4.z;
                oacc0[d4 * 4 + 3] += p0 * v4.w; oacc1[d4 * 4 + 3] += p1 * v4.w;
            }
        }
        __syncthreads();
    }

    {
        int tok0 = sidx_sh[n * 64 + tq * 2 + 0];
        int tok1 = sidx_sh[n * 64 + tq * 2 + 1];
        size_t base0 = ((size_t)seg * S_DIM + tok0) * D_DIM + td * 16;
        size_t base1 = ((size_t)seg * S_DIM + tok1) * D_DIM + td * 16;
#pragma unroll
        for (int d4 = 0; d4 < 4; d4++) {
            *(float4*)&g_oout[base0 + d4 * 4] =
                make_float4(oacc0[d4*4+0], oacc0[d4*4+1], oacc0[d4*4+2], oacc0[d4*4+3]);
            *(float4*)&g_oout[base1 + d4 * 4] =
                make_float4(oacc1[d4*4+0], oacc1[d4*4+1], oacc1[d4*4+2], oacc1[d4*4+3]);
        }
    }
}

// ---------------- combine rounds by softmax over lse ----------------
// grid: B*H*S blocks, 128 threads (one per d).
__global__ void combine_kernel()
{
    const int idx = blockIdx.x;
    const int s = idx % S_DIM;
    const int bh = idx / S_DIM;
    const int b = bh / H_DIM, h = bh % H_DIM;
    const int seg0 = (b * R_DIM + 0) * H_DIM + h;
    const int seg1 = (b * R_DIM + 1) * H_DIM + h;

    float l0 = g_olse[(size_t)seg0 * S_DIM + s];
    float l1 = g_olse[(size_t)seg1 * S_DIM + s];
    float m = fmaxf(l0, l1);
    float e0 = expf(l0 - m), e1 = expf(l1 - m);
    float inv = 1.0f / (e0 + e1);

    const int d = threadIdx.x;
    float o0 = g_oout[((size_t)seg0 * S_DIM + s) * D_DIM + d];
    float o1 = g_oout[((size_t)seg1 * S_DIM + s) * D_DIM + d];
    g_ocomb[((size_t)s * B_DIM + b) * E_DIM + h * D_DIM + d] = (e0 * o0 + e1 * o1) * inv;
}

// ---------------- launcher ----------------
extern "C" void kernel_launch(void* const* d_in, const int* in_sizes, int n_in,
                              void* d_out, int out_size)
{
    const float* x      = (const float*)d_in[0];
    const float* wq     = (const float*)d_in[1];
    const float* bq     = (const float*)d_in[2];
    const float* wv     = (const float*)d_in[3];
    const float* bv     = (const float*)d_in[4];
    const float* wo     = (const float*)d_in[5];
    const float* bo     = (const float*)d_in[6];
    const float* hash_w = (const float*)d_in[7];
    float* out = (float*)d_out;

    float *p_qraw, *p_v, *p_ocomb;
    cudaGetSymbolAddress((void**)&p_qraw,  g_qraw);
    cudaGetSymbolAddress((void**)&p_v,     g_v);
    cudaGetSymbolAddress((void**)&p_ocomb, g_ocomb);

    cudaFuncSetAttribute(attn_kernel, cudaFuncAttributeMaxDynamicSharedMemorySize,
                         ATTN_SMEM);

    dim3 gemm_grid(E_DIM / 64, MROWS / 128);

    gemm_bias_kernel<<<gemm_grid, 256>>>(x, wq, bq, p_qraw, MROWS, E_DIM, E_DIM);
    gemm_bias_kernel<<<gemm_grid, 256>>>(x, wv, bv, p_v,    MROWS, E_DIM, E_DIM);
    norm_kernel<<<MROWS, 256>>>();
    hash_kernel<<<dim3(S_DIM / 256, NSEG), 256>>>(hash_w);
    sort_kernel<<<NSEG, 512>>>();
    attn_kernel<<<NSEG * NC_DIM, 256, ATTN_SMEM>>>();
    combine_kernel<<<B_DIM * H_DIM * S_DIM, 128>>>();
    gemm_bias_kernel<<<gemm_grid, 256>>>(p_ocomb, wo, bo, out, MROWS, E_DIM, E_DIM);
}

// round 5
// speedup vs baseline: 1.0274x; 1.0274x over previous
#include <cuda_runtime.h>
#include <math.h>

// ---------------- problem dims ----------------
#define S_DIM 4096
#define B_DIM 2
#define E_DIM 1024
#define H_DIM 8
#define R_DIM 2
#define C_DIM 64
#define D_DIM 128
#define NC_DIM 64                    // S / C
#define NSEG (B_DIM*R_DIM*H_DIM)     // 32
#define MROWS (S_DIM*B_DIM)          // 8192
#define SCALE_F 0.08838834764831845f // D^-0.5
#define NEG_F (-1e9f)
#define NEG_SELF_F (-1e5f)

// ---------------- scratch (device globals; no allocation) ----------------
__device__ float g_qraw[MROWS*E_DIM];     // x@wq^T + bq
__device__ float g_k[MROWS*E_DIM];        // qraw / ||qraw||_E
__device__ float g_v[MROWS*E_DIM];        // x@wv^T + bv
__device__ float g_ocomb[MROWS*E_DIM];    // combined heads, [S,B,E]
__device__ float g_oout[NSEG*S_DIM*D_DIM];// per-(b,r,h) outputs, original token order
__device__ float g_olse[NSEG*S_DIM];      // per-(b,r,h) lse, original token order
__device__ int   g_hash[NSEG*S_DIM];
__device__ int   g_sidx[NSEG*S_DIM];      // sorted token ids
__device__ int   g_shash[NSEG*S_DIM];     // sorted hash values

// =====================================================================
// SIMT fp32 GEMM for the q projection ONLY.
// The LSH bucket argmax + stable sort amplify ANY q perturbation: one
// flipped hash shifts sort positions of all later tokens in the segment
// (slot-indexed masks), so q must match the fp32 reference to ~1e-7.
// Tensor-core tf32 (even 3-pass split) changes accumulation enough to
// flip near-ties -> keep q on the fp32 FMA pipe.
// BM=128, BN=64, BK=16, 256 threads, 8x4 per-thread micro-tile.
// =====================================================================
__global__ void gemm_bias_kernel(const float* __restrict__ A,
                                 const float* __restrict__ W,
                                 const float* __restrict__ bias,
                                 float* __restrict__ C,
                                 int M, int N, int K)
{
    __shared__ float As[16][132];  // [k][m], padded
    __shared__ float Ws[16][68];   // [k][n], padded

    const int tid = threadIdx.x;
    const int bm = blockIdx.y * 128;
    const int bn = blockIdx.x * 64;
    const int tm = tid >> 4;   // 0..15 -> rows tm*8..tm*8+7
    const int tn = tid & 15;   // 0..15 -> cols tn*4..tn*4+3

    float acc[8][4];
#pragma unroll
    for (int i = 0; i < 8; i++)
#pragma unroll
        for (int j = 0; j < 4; j++) acc[i][j] = 0.f;

    for (int k0 = 0; k0 < K; k0 += 16) {
#pragma unroll
        for (int it = 0; it < 2; it++) {
            int l = it * 256 + tid;
            int m = l >> 2, kq = (l & 3) * 4;
            float4 va = *(const float4*)&A[(size_t)(bm + m) * K + k0 + kq];
            As[kq + 0][m] = va.x; As[kq + 1][m] = va.y;
            As[kq + 2][m] = va.z; As[kq + 3][m] = va.w;
        }
        {
            int n = tid >> 2, kq = (tid & 3) * 4;
            float4 vw = *(const float4*)&W[(size_t)(bn + n) * K + k0 + kq];
            Ws[kq + 0][n] = vw.x; Ws[kq + 1][n] = vw.y;
            Ws[kq + 2][n] = vw.z; Ws[kq + 3][n] = vw.w;
        }
        __syncthreads();

#pragma unroll
        for (int k = 0; k < 16; k++) {
            float4 a0 = *(const float4*)&As[k][tm * 8];
            float4 a1 = *(const float4*)&As[k][tm * 8 + 4];
            float4 b0 = *(const float4*)&Ws[k][tn * 4];
            float av[8] = {a0.x, a0.y, a0.z, a0.w, a1.x, a1.y, a1.z, a1.w};
            float bv[4] = {b0.x, b0.y, b0.z, b0.w};
#pragma unroll
            for (int i = 0; i < 8; i++)
#pragma unroll
                for (int j = 0; j < 4; j++) acc[i][j] += av[i] * bv[j];
        }
        __syncthreads();
    }

    float4 bb = *(const float4*)&bias[bn + tn * 4];
#pragma unroll
    for (int i = 0; i < 8; i++) {
        float4 o;
        o.x = acc[i][0] + bb.x; o.y = acc[i][1] + bb.y;
        o.z = acc[i][2] + bb.z; o.w = acc[i][3] + bb.w;
        *(float4*)&C[(size_t)(bm + tm * 8 + i) * N + bn + tn * 4] = o;
    }
}

// =====================================================================
// Split tf32 tensor-core GEMM for v and o projections (no discrete
// decisions downstream -> smooth ~1e-6 errors are fine).
// C[M,N] = A[M,K] @ W[N,K]^T + bias[N]
// hi = bitwise truncation to tf32; lo = x - hi (fp32-exact).
// acc = hi*hi + hi*lo + lo*hi.
// =====================================================================
__device__ __forceinline__ unsigned hi_tf(float x) {
    return __float_as_uint(x) & 0xFFFFE000u;
}

__device__ __forceinline__ void mma8(float* d, const unsigned* a, const unsigned* b) {
    asm volatile(
        "mma.sync.aligned.m16n8k8.row.col.f32.tf32.tf32.f32 "
        "{%0,%1,%2,%3}, {%4,%5,%6,%7}, {%8,%9}, {%0,%1,%2,%3};\n"
        : "+f"(d[0]), "+f"(d[1]), "+f"(d[2]), "+f"(d[3])
        : "r"(a[0]), "r"(a[1]), "r"(a[2]), "r"(a[3]), "r"(b[0]), "r"(b[1]));
}

#define BKS 36

__global__ void __launch_bounds__(256, 1)
gemm_tf32_kernel(const float* __restrict__ A,
                 const float* __restrict__ W,
                 const float* __restrict__ bias,
                 float* __restrict__ C,
                 int M, int N, int K)
{
    extern __shared__ unsigned smu[];
    unsigned* Ah = smu;                 // [128*BKS]
    unsigned* Wh = Ah + 128 * BKS;
    unsigned* Al = Wh + 128 * BKS;
    unsigned* Wl = Al + 128 * BKS;

    const int tid = threadIdx.x;
    const int wid = tid >> 5, lane = tid & 31;
    const int gid = lane >> 2, tig = lane & 3;
    const int warp_m = wid & 1;
    const int warp_n = wid >> 1;
    const int bm = blockIdx.y * 128, bn = blockIdx.x * 128;

    float acc[4][4][4];
#pragma unroll
    for (int mi = 0; mi < 4; mi++)
#pragma unroll
        for (int ni = 0; ni < 4; ni++)
#pragma unroll
            for (int r = 0; r < 4; r++) acc[mi][ni][r] = 0.f;

    for (int k0 = 0; k0 < K; k0 += 32) {
#pragma unroll
        for (int it = 0; it < 4; it++) {
            int t = it * 256 + tid;
            int row = t >> 3, cq = (t & 7) * 4;
            float4 va = *(const float4*)&A[(size_t)(bm + row) * K + k0 + cq];
            float4 vw = *(const float4*)&W[(size_t)(bn + row) * K + k0 + cq];
            unsigned* ap  = &Ah[row * BKS + cq];
            unsigned* wp  = &Wh[row * BKS + cq];
            unsigned* alp = &Al[row * BKS + cq];
            unsigned* wlp = &Wl[row * BKS + cq];
            unsigned ha0 = hi_tf(va.x), ha1 = hi_tf(va.y), ha2 = hi_tf(va.z), ha3 = hi_tf(va.w);
            unsigned hw0 = hi_tf(vw.x), hw1 = hi_tf(vw.y), hw2 = hi_tf(vw.z), hw3 = hi_tf(vw.w);
            ap[0] = ha0; ap[1] = ha1; ap[2] = ha2; ap[3] = ha3;
            wp[0] = hw0; wp[1] = hw1; wp[2] = hw2; wp[3] = hw3;
            alp[0] = __float_as_uint(va.x - __uint_as_float(ha0));
            alp[1] = __float_as_uint(va.y - __uint_as_float(ha1));
            alp[2] = __float_as_uint(va.z - __uint_as_float(ha2));
            alp[3] = __float_as_uint(va.w - __uint_as_float(ha3));
            wlp[0] = __float_as_uint(vw.x - __uint_as_float(hw0));
            wlp[1] = __float_as_uint(vw.y - __uint_as_float(hw1));
            wlp[2] = __float_as_uint(vw.z - __uint_as_float(hw2));
            wlp[3] = __float_as_uint(vw.w - __uint_as_float(hw3));
        }
        __syncthreads();

#pragma unroll
        for (int kk = 0; kk < 4; kk++) {
            const int k = kk * 8;
            unsigned af[4][4], bf[4][2];
#pragma unroll
            for (int mi = 0; mi < 4; mi++) {
                int rb = warp_m * 64 + mi * 16;
                af[mi][0] = Ah[(rb + gid)     * BKS + k + tig];
                af[mi][1] = Ah[(rb + gid + 8) * BKS + k + tig];
                af[mi][2] = Ah[(rb + gid)     * BKS + k + tig + 4];
                af[mi][3] = Ah[(rb + gid + 8) * BKS + k + tig + 4];
            }
#pragma unroll
            for (int ni = 0; ni < 4; ni++) {
                int nb = warp_n * 32 + ni * 8;
                bf[ni][0] = Wh[(nb + gid) * BKS + k + tig];
                bf[ni][1] = Wh[(nb + gid) * BKS + k + tig + 4];
            }
#pragma unroll
            for (int mi = 0; mi < 4; mi++)
#pragma unroll
                for (int ni = 0; ni < 4; ni++)
                    mma8(acc[mi][ni], af[mi], bf[ni]);

            unsigned bl[4][2];
#pragma unroll
            for (int ni = 0; ni < 4; ni++) {
                int nb = warp_n * 32 + ni * 8;
                bl[ni][0] = Wl[(nb + gid) * BKS + k + tig];
                bl[ni][1] = Wl[(nb + gid) * BKS + k + tig + 4];
            }
#pragma unroll
            for (int mi = 0; mi < 4; mi++)
#pragma unroll
                for (int ni = 0; ni < 4; ni++)
                    mma8(acc[mi][ni], af[mi], bl[ni]);

#pragma unroll
            for (int mi = 0; mi < 4; mi++) {
                int rb = warp_m * 64 + mi * 16;
                af[mi][0] = Al[(rb + gid)     * BKS + k + tig];
                af[mi][1] = Al[(rb + gid + 8) * BKS + k + tig];
                af[mi][2] = Al[(rb + gid)     * BKS + k + tig + 4];
                af[mi][3] = Al[(rb + gid + 8) * BKS + k + tig + 4];
            }
#pragma unroll
            for (int mi = 0; mi < 4; mi++)
#pragma unroll
                for (int ni = 0; ni < 4; ni++)
                    mma8(acc[mi][ni], af[mi], bf[ni]);
        }
        __syncthreads();
    }

#pragma unroll
    for (int mi = 0; mi < 4; mi++) {
        int m0 = bm + warp_m * 64 + mi * 16 + gid;
#pragma unroll
        for (int ni = 0; ni < 4; ni++) {
            int n0 = bn + warp_n * 32 + ni * 8 + tig * 2;
            float b0 = bias[n0], b1 = bias[n0 + 1];
            float2 r0 = make_float2(acc[mi][ni][0] + b0, acc[mi][ni][1] + b1);
            float2 r1 = make_float2(acc[mi][ni][2] + b0, acc[mi][ni][3] + b1);
            *(float2*)&C[(size_t)m0 * N + n0] = r0;
            *(float2*)&C[(size_t)(m0 + 8) * N + n0] = r1;
        }
    }
}

#define GEMM_SMEM (4 * 128 * BKS * 4)

// ---------------- k = q / ||q||  (norm over full E) ----------------
__global__ void norm_kernel()
{
    const int row = blockIdx.x;
    const float* q = g_qraw + (size_t)row * E_DIM;
    float ss = 0.f;
    for (int i = threadIdx.x; i < E_DIM; i += 256) { float v = q[i]; ss += v * v; }
#pragma unroll
    for (int o = 16; o > 0; o >>= 1) ss += __shfl_xor_sync(0xffffffffu, ss, o);
    __shared__ float red[8];
    __shared__ float s_inv;
    if ((threadIdx.x & 31) == 0) red[threadIdx.x >> 5] = ss;
    __syncthreads();
    if (threadIdx.x == 0) {
        float t = 0.f;
#pragma unroll
        for (int i = 0; i < 8; i++) t += red[i];
        s_inv = 1.0f / sqrtf(t);
    }
    __syncthreads();
    const float inv = s_inv;
    for (int i = threadIdx.x; i < E_DIM; i += 256)
        g_k[(size_t)row * E_DIM + i] = q[i] * inv;
}

// ---------------- LSH hashing: argmax over [lin, -lin] ----------------
__global__ void hash_kernel(const float* __restrict__ hash_w)
{
    const int seg = blockIdx.y;              // (b*R + r)*H + h
    const int b = seg / (R_DIM * H_DIM);
    const int r = (seg / H_DIM) % R_DIM;
    const int h = seg % H_DIM;

    __shared__ float hw[D_DIM * 8];          // hash_w[r][h][d][m]
    const float* hwp = hash_w + (size_t)(r * H_DIM + h) * D_DIM * 8;
    for (int i = threadIdx.x; i < D_DIM * 8; i += 256) hw[i] = hwp[i];
    __syncthreads();

    const int s = blockIdx.x * 256 + threadIdx.x;
    const float* qp = g_qraw + ((size_t)s * B_DIM + b) * E_DIM + h * D_DIM;

    float acc[8];
#pragma unroll
    for (int m = 0; m < 8; m++) acc[m] = 0.f;
    for (int d = 0; d < D_DIM; d++) {
        float qv = qp[d];
#pragma unroll
        for (int m = 0; m < 8; m++) acc[m] += qv * hw[d * 8 + m];
    }
    float best = acc[0]; int bi = 0;
#pragma unroll
    for (int m = 1; m < 8; m++) if (acc[m] > best) { best = acc[m]; bi = m; }
#pragma unroll
    for (int m = 0; m < 8; m++) if (-acc[m] > best) { best = -acc[m]; bi = 8 + m; }
    g_hash[(size_t)seg * S_DIM + s] = bi;
}

// ---------------- stable counting sort (16 buckets) ----------------
__global__ void sort_kernel()
{
    const int seg = blockIdx.x;
    const int tid = threadIdx.x;
    __shared__ int tc[512][16];
    __shared__ int base[16], tot[16];

    const int* hp = g_hash + (size_t)seg * S_DIM;
#pragma unroll
    for (int m = 0; m < 16; m++) tc[tid][m] = 0;
    int myh[8];
#pragma unroll
    for (int i = 0; i < 8; i++) {
        myh[i] = hp[tid * 8 + i];
        tc[tid][myh[i]]++;
    }
    __syncthreads();
    if (tid < 16) {
        int run = 0;
        for (int t = 0; t < 512; t++) { int v = tc[t][tid]; tc[t][tid] = run; run += v; }
        tot[tid] = run;
    }
    __syncthreads();
    if (tid == 0) {
        int run = 0;
#pragma unroll
        for (int m = 0; m < 16; m++) { base[m] = run; run += tot[m]; }
    }
    __syncthreads();
#pragma unroll
    for (int i = 0; i < 8; i++) {
        int hh = myh[i];
        int pos = base[hh] + tc[tid][hh];
        tc[tid][hh]++;
        g_sidx[(size_t)seg * S_DIM + pos]  = tid * 8 + i;
        g_shash[(size_t)seg * S_DIM + pos] = hh;
    }
}

// ---------------- chunked LSH attention ----------------
// one block per (seg, chunk). 256 threads.
// reference-broadcast semantics: mask windows are indexed by the query's
// SLOT c within its chunk (C == n_c), so each block stages the segment's
// full sorted hash/idx arrays in shared.
#define QS 132
#define LGS 196
#define ATTN_SMEM ((2*64*QS + 64*LGS) * 4 + 2 * S_DIM * 4)

__global__ void attn_kernel()
{
    extern __shared__ float sm[];
    float* q_sh  = sm;                      // [64][QS]
    float* kv_sh = sm + 64 * QS;            // [64][QS]
    float* lg    = sm + 2 * 64 * QS;        // [64][LGS]
    int* sidx_sh  = (int*)(sm + 2 * 64 * QS + 64 * LGS);  // [4096]
    int* shash_sh = sidx_sh + S_DIM;                       // [4096]

    const int bid = blockIdx.x;
    const int n   = bid % NC_DIM;
    const int seg = bid / NC_DIM;           // (b*R + r)*H + h
    const int b   = seg / (R_DIM * H_DIM);
    const int h   = seg % H_DIM;
    const int tid = threadIdx.x;

    const int* gsidx  = g_sidx  + (size_t)seg * S_DIM;
    const int* gshash = g_shash + (size_t)seg * S_DIM;
    for (int i = tid; i < S_DIM; i += 256) {
        sidx_sh[i]  = gsidx[i];
        shash_sh[i] = gshash[i];
    }
    __syncthreads();

    // load q (scaled)
    for (int idx = tid; idx < 64 * 128; idx += 256) {
        int qi = idx >> 7, d = idx & 127;
        int tok = sidx_sh[n * 64 + qi];
        q_sh[qi * QS + d] =
            SCALE_F * g_qraw[((size_t)tok * B_DIM + b) * E_DIM + h * D_DIM + d];
    }

    // ---- logits: 3 chunks of 64 keys (K window of chunk n) ----
    const int tqi = tid >> 4;   // 0..15 -> queries tqi*4..+3
    const int tj  = tid & 15;   // 0..15 -> keys    tj*4..+3
    for (int c = 0; c < 3; c++) {
        __syncthreads();
        int kchunk = (n + c + NC_DIM - 1) % NC_DIM;
        for (int idx = tid; idx < 64 * 128; idx += 256) {
            int j = idx >> 7, d = idx & 127;
            int tok = sidx_sh[kchunk * 64 + j];
            kv_sh[j * QS + d] =
                g_k[((size_t)tok * B_DIM + b) * E_DIM + h * D_DIM + d];
        }
        __syncthreads();

        float lacc[4][4];
#pragma unroll
        for (int i = 0; i < 4; i++)
#pragma unroll
            for (int j = 0; j < 4; j++) lacc[i][j] = 0.f;

        for (int d4 = 0; d4 < 32; d4++) {
            float4 qv[4], kv4[4];
#pragma unroll
            for (int i = 0; i < 4; i++)
                qv[i] = *(const float4*)&q_sh[(tqi * 4 + i) * QS + d4 * 4];
#pragma unroll
            for (int j = 0; j < 4; j++)
                kv4[j] = *(const float4*)&kv_sh[(tj * 4 + j) * QS + d4 * 4];
#pragma unroll
            for (int i = 0; i < 4; i++)
#pragma unroll
                for (int j = 0; j < 4; j++)
                    lacc[i][j] += qv[i].x * kv4[j].x + qv[i].y * kv4[j].y +
                                  qv[i].z * kv4[j].z + qv[i].w * kv4[j].w;
        }
#pragma unroll
        for (int i = 0; i < 4; i++) {
            int qq = tqi * 4 + i;                    // slot within chunk
            int qpos = n * 64 + qq;                  // sorted position of query
            int qhash = shash_sh[qpos];
            int qtok  = sidx_sh[qpos];
            // MASK window is chunk index == slot qq (reference broadcast artifact)
            int mchunk = (qq + c + NC_DIM - 1) % NC_DIM;
#pragma unroll
            for (int j = 0; j < 4; j++) {
                int jj = tj * 4 + j;
                int mpos = mchunk * 64 + jj;
                float lv = lacc[i][j];
                if (qhash != shash_sh[mpos]) lv = NEG_F;      // different hash
                if (qtok  == sidx_sh[mpos])  lv = NEG_SELF_F; // "self"
                lg[qq * LGS + c * 64 + jj] = lv;
            }
        }
    }
    __syncthreads();

    // ---- softmax + lse per query row ----
    if (tid < 64) {
        float m = -3.402823466e38f;
        for (int j = 0; j < 192; j++) m = fmaxf(m, lg[tid * LGS + j]);
        float ssum = 0.f;
        for (int j = 0; j < 192; j++) {
            float e = expf(lg[tid * LGS + j] - m);
            lg[tid * LGS + j] = e;
            ssum += e;
        }
        float inv = 1.0f / ssum;
        for (int j = 0; j < 192; j++) lg[tid * LGS + j] *= inv;
        g_olse[(size_t)seg * S_DIM + sidx_sh[n * 64 + tid]] = m + logf(ssum);
    }
    __syncthreads();

    // ---- output: o = P @ V, scattered to original token order ----
    const int tq = tid >> 3;   // 0..31 -> queries tq*2, tq*2+1
    const int td = tid & 7;    // 0..7  -> dims td*16..td*16+15
    float oacc0[16], oacc1[16];
#pragma unroll
    for (int u = 0; u < 16; u++) { oacc0[u] = 0.f; oacc1[u] = 0.f; }

    for (int c = 0; c < 3; c++) {
        int kchunk = (n + c + NC_DIM - 1) % NC_DIM;
        for (int idx = tid; idx < 64 * 128; idx += 256) {
            int j = idx >> 7, d = idx & 127;
            int tok = sidx_sh[kchunk * 64 + j];
            kv_sh[j * QS + d] =
                g_v[((size_t)tok * B_DIM + b) * E_DIM + h * D_DIM + d];
        }
        __syncthreads();
        for (int j = 0; j < 64; j++) {
            float p0 = lg[(tq * 2 + 0) * LGS + c * 64 + j];
            float p1 = lg[(tq * 2 + 1) * LGS + c * 64 + j];
            const float* vrow = &kv_sh[j * QS + td * 16];
#pragma unroll
            for (int d4 = 0; d4 < 4; d4++) {
                float4 v4 = *(const float4*)&vrow[d4 * 4];
                oacc0[d4 * 4 + 0] += p0 * v4.x; oacc1[d4 * 4 + 0] += p1 * v4.x;
                oacc0[d4 * 4 + 1] += p0 * v4.y; oacc1[d4 * 4 + 1] += p1 * v4.y;
                oacc0[d4 * 4 + 2] += p0 * v4.z; oacc1[d4 * 4 + 2] += p1 * v4.z;
                oacc0[d4 * 4 + 3] += p0 * v4.w; oacc1[d4 * 4 + 3] += p1 * v4.w;
            }
        }
        __syncthreads();
    }

    {
        int tok0 = sidx_sh[n * 64 + tq * 2 + 0];
        int tok1 = sidx_sh[n * 64 + tq * 2 + 1];
        size_t base0 = ((size_t)seg * S_DIM + tok0) * D_DIM + td * 16;
        size_t base1 = ((size_t)seg * S_DIM + tok1) * D_DIM + td * 16;
#pragma unroll
        for (int d4 = 0; d4 < 4; d4++) {
            *(float4*)&g_oout[base0 + d4 * 4] =
                make_float4(oacc0[d4*4+0], oacc0[d4*4+1], oacc0[d4*4+2], oacc0[d4*4+3]);
            *(float4*)&g_oout[base1 + d4 * 4] =
                make_float4(oacc1[d4*4+0], oacc1[d4*4+1], oacc1[d4*4+2], oacc1[d4*4+3]);
        }
    }
}

// ---------------- combine rounds by softmax over lse ----------------
__global__ void combine_kernel()
{
    const int idx = blockIdx.x;
    const int s = idx % S_DIM;
    const int bh = idx / S_DIM;
    const int b = bh / H_DIM, h = bh % H_DIM;
    const int seg0 = (b * R_DIM + 0) * H_DIM + h;
    const int seg1 = (b * R_DIM + 1) * H_DIM + h;

    float l0 = g_olse[(size_t)seg0 * S_DIM + s];
    float l1 = g_olse[(size_t)seg1 * S_DIM + s];
    float m = fmaxf(l0, l1);
    float e0 = expf(l0 - m), e1 = expf(l1 - m);
    float inv = 1.0f / (e0 + e1);

    const int d = threadIdx.x;
    float o0 = g_oout[((size_t)seg0 * S_DIM + s) * D_DIM + d];
    float o1 = g_oout[((size_t)seg1 * S_DIM + s) * D_DIM + d];
    g_ocomb[((size_t)s * B_DIM + b) * E_DIM + h * D_DIM + d] = (e0 * o0 + e1 * o1) * inv;
}

// ---------------- launcher ----------------
extern "C" void kernel_launch(void* const* d_in, const int* in_sizes, int n_in,
                              void* d_out, int out_size)
{
    const float* x      = (const float*)d_in[0];
    const float* wq     = (const float*)d_in[1];
    const float* bq     = (const float*)d_in[2];
    const float* wv     = (const float*)d_in[3];
    const float* bv     = (const float*)d_in[4];
    const float* wo     = (const float*)d_in[5];
    const float* bo     = (const float*)d_in[6];
    const float* hash_w = (const float*)d_in[7];
    float* out = (float*)d_out;

    float *p_qraw, *p_v, *p_ocomb;
    cudaGetSymbolAddress((void**)&p_qraw,  g_qraw);
    cudaGetSymbolAddress((void**)&p_v,     g_v);
    cudaGetSymbolAddress((void**)&p_ocomb, g_ocomb);

    cudaFuncSetAttribute(attn_kernel, cudaFuncAttributeMaxDynamicSharedMemorySize,
                         ATTN_SMEM);
    cudaFuncSetAttribute(gemm_tf32_kernel,
                         cudaFuncAttributeMaxDynamicSharedMemorySize, GEMM_SMEM);

    dim3 grid_simt(E_DIM / 64, MROWS / 128);
    dim3 grid_tc(E_DIM / 128, MROWS / 128);

    // q: SIMT fp32 (hash argmax + sort need fp32-exact-level q)
    gemm_bias_kernel<<<grid_simt, 256>>>(x, wq, bq, p_qraw, MROWS, E_DIM, E_DIM);
    // v: split tf32 on tensor pipe
    gemm_tf32_kernel<<<grid_tc, 256, GEMM_SMEM>>>(x, wv, bv, p_v,
                                                  MROWS, E_DIM, E_DIM);
    norm_kernel<<<MROWS, 256>>>();
    hash_kernel<<<dim3(S_DIM / 256, NSEG), 256>>>(hash_w);
    sort_kernel<<<NSEG, 512>>>();
    attn_kernel<<<NSEG * NC_DIM, 256, ATTN_SMEM>>>();
    combine_kernel<<<B_DIM * H_DIM * S_DIM, 128>>>();
    // o: split tf32 on tensor pipe
    gemm_tf32_kernel<<<grid_tc, 256, GEMM_SMEM>>>(p_ocomb, wo, bo, out,
                                                  MROWS, E_DIM, E_DIM);
}

// round 6
// speedup vs baseline: 1.2719x; 1.2379x over previous
#include <cuda_runtime.h>
#include <math.h>

// ---------------- problem dims ----------------
#define S_DIM 4096
#define B_DIM 2
#define E_DIM 1024
#define H_DIM 8
#define R_DIM 2
#define C_DIM 64
#define D_DIM 128
#define NC_DIM 64                    // S / C
#define NSEG (B_DIM*R_DIM*H_DIM)     // 32
#define MROWS (S_DIM*B_DIM)          // 8192
#define SCALE_F 0.08838834764831845f // D^-0.5
#define NEG_F (-1e9f)
#define NEG_SELF_F (-1e5f)

// ---------------- scratch (device globals; no allocation) ----------------
__device__ float g_qraw[MROWS*E_DIM];     // x@wq^T + bq
__device__ float g_k[MROWS*E_DIM];        // qraw / ||qraw||_E
__device__ float g_v[MROWS*E_DIM];        // x@wv^T + bv
__device__ float g_ocomb[MROWS*E_DIM];    // combined heads, [S,B,E]
__device__ float g_oout[NSEG*S_DIM*D_DIM];// per-(b,r,h) outputs, original token order
__device__ float g_olse[NSEG*S_DIM];      // per-(b,r,h) lse, original token order
__device__ int   g_hash[NSEG*S_DIM];
__device__ int   g_sidx[NSEG*S_DIM];      // sorted token ids
__device__ int   g_shash[NSEG*S_DIM];     // sorted hash values

// =====================================================================
// SIMT fp32 GEMM v2: C[M,N] = A[M,K] @ W[N,K]^T + bias[N]
// BM=128, BN=128, BK=16, 256 threads, 8x8 micro-tile, double-buffered
// smem with register-held global prefetch. Accumulation is k-ascending
// per output element -> numerics identical to the flip-free q path.
// (mma.sync tf32 measured ~SIMT rate on sm_103a -> not used.)
// =====================================================================
__global__ void __launch_bounds__(256)
gemm_bias_kernel(const float* __restrict__ A,
                 const float* __restrict__ W,
                 const float* __restrict__ bias,
                 float* __restrict__ C,
                 int M, int N, int K)
{
    __shared__ float As[2][16][132];  // [buf][k][m]
    __shared__ float Ws[2][16][132];  // [buf][k][n]

    const int tid = threadIdx.x;
    const int bm = blockIdx.y * 128;
    const int bn = blockIdx.x * 128;
    const int tm = tid >> 4;   // 0..15 -> rows tm*8..+7
    const int tn = tid & 15;   // 0..15 -> cols tn*8..+7

    float acc[8][8];
#pragma unroll
    for (int i = 0; i < 8; i++)
#pragma unroll
        for (int j = 0; j < 8; j++) acc[i][j] = 0.f;

    float4 ha[2], hw[2];
    const int m0l = (tid * 4) >> 4;        // precompute per-thread staging coords
    // staging map: l = it*256 + tid; m = l>>2; kq = (l&3)*4

#define GLD(k0)                                                            \
    {                                                                      \
        _Pragma("unroll")                                                  \
        for (int it = 0; it < 2; it++) {                                   \
            int l = it * 256 + tid; int m = l >> 2; int kq = (l & 3) * 4;  \
            ha[it] = *(const float4*)&A[(size_t)(bm + m) * K + (k0) + kq]; \
            hw[it] = *(const float4*)&W[(size_t)(bn + m) * K + (k0) + kq]; \
        }                                                                  \
    }
#define GST(nb)                                                            \
    {                                                                      \
        _Pragma("unroll")                                                  \
        for (int it = 0; it < 2; it++) {                                   \
            int l = it * 256 + tid; int m = l >> 2; int kq = (l & 3) * 4;  \
            As[nb][kq + 0][m] = ha[it].x; As[nb][kq + 1][m] = ha[it].y;    \
            As[nb][kq + 2][m] = ha[it].z; As[nb][kq + 3][m] = ha[it].w;    \
            Ws[nb][kq + 0][m] = hw[it].x; Ws[nb][kq + 1][m] = hw[it].y;    \
            Ws[nb][kq + 2][m] = hw[it].z; Ws[nb][kq + 3][m] = hw[it].w;    \
        }                                                                  \
    }

    (void)m0l;
    GLD(0); GST(0); __syncthreads();

    const int nIter = K >> 4;
    for (int ii = 0; ii < nIter; ii++) {
        if (ii + 1 < nIter) GLD((ii + 1) << 4);
        const int cb = ii & 1;
#pragma unroll
        for (int k = 0; k < 16; k++) {
            float4 a0 = *(const float4*)&As[cb][k][tm * 8];
            float4 a1 = *(const float4*)&As[cb][k][tm * 8 + 4];
            float4 b0 = *(const float4*)&Ws[cb][k][tn * 8];
            float4 b1 = *(const float4*)&Ws[cb][k][tn * 8 + 4];
            float av[8] = {a0.x, a0.y, a0.z, a0.w, a1.x, a1.y, a1.z, a1.w};
            float bv[8] = {b0.x, b0.y, b0.z, b0.w, b1.x, b1.y, b1.z, b1.w};
#pragma unroll
            for (int i = 0; i < 8; i++)
#pragma unroll
                for (int j = 0; j < 8; j++) acc[i][j] += av[i] * bv[j];
        }
        if (ii + 1 < nIter) GST((ii + 1) & 1);
        __syncthreads();
    }
#undef GLD
#undef GST

    float4 bb0 = *(const float4*)&bias[bn + tn * 8];
    float4 bb1 = *(const float4*)&bias[bn + tn * 8 + 4];
#pragma unroll
    for (int i = 0; i < 8; i++) {
        float4 o0, o1;
        o0.x = acc[i][0] + bb0.x; o0.y = acc[i][1] + bb0.y;
        o0.z = acc[i][2] + bb0.z; o0.w = acc[i][3] + bb0.w;
        o1.x = acc[i][4] + bb1.x; o1.y = acc[i][5] + bb1.y;
        o1.z = acc[i][6] + bb1.z; o1.w = acc[i][7] + bb1.w;
        size_t rowoff = (size_t)(bm + tm * 8 + i) * N + bn + tn * 8;
        *(float4*)&C[rowoff]     = o0;
        *(float4*)&C[rowoff + 4] = o1;
    }
}

// ---------------- k = q / ||q||  (norm over full E) ----------------
__global__ void norm_kernel()
{
    const int row = blockIdx.x;
    const float* q = g_qraw + (size_t)row * E_DIM;
    float ss = 0.f;
    for (int i = threadIdx.x; i < E_DIM; i += 256) { float v = q[i]; ss += v * v; }
#pragma unroll
    for (int o = 16; o > 0; o >>= 1) ss += __shfl_xor_sync(0xffffffffu, ss, o);
    __shared__ float red[8];
    __shared__ float s_inv;
    if ((threadIdx.x & 31) == 0) red[threadIdx.x >> 5] = ss;
    __syncthreads();
    if (threadIdx.x == 0) {
        float t = 0.f;
#pragma unroll
        for (int i = 0; i < 8; i++) t += red[i];
        s_inv = 1.0f / sqrtf(t);
    }
    __syncthreads();
    const float inv = s_inv;
    for (int i = threadIdx.x; i < E_DIM; i += 256)
        g_k[(size_t)row * E_DIM + i] = q[i] * inv;
}

// ---------------- LSH hashing: argmax over [lin, -lin] ----------------
__global__ void hash_kernel(const float* __restrict__ hash_w)
{
    const int seg = blockIdx.y;              // (b*R + r)*H + h
    const int b = seg / (R_DIM * H_DIM);
    const int r = (seg / H_DIM) % R_DIM;
    const int h = seg % H_DIM;

    __shared__ float hw[D_DIM * 8];          // hash_w[r][h][d][m]
    const float* hwp = hash_w + (size_t)(r * H_DIM + h) * D_DIM * 8;
    for (int i = threadIdx.x; i < D_DIM * 8; i += 256) hw[i] = hwp[i];
    __syncthreads();

    const int s = blockIdx.x * 256 + threadIdx.x;
    const float* qp = g_qraw + ((size_t)s * B_DIM + b) * E_DIM + h * D_DIM;

    float acc[8];
#pragma unroll
    for (int m = 0; m < 8; m++) acc[m] = 0.f;
    for (int d = 0; d < D_DIM; d++) {
        float qv = qp[d];
#pragma unroll
        for (int m = 0; m < 8; m++) acc[m] += qv * hw[d * 8 + m];
    }
    float best = acc[0]; int bi = 0;
#pragma unroll
    for (int m = 1; m < 8; m++) if (acc[m] > best) { best = acc[m]; bi = m; }
#pragma unroll
    for (int m = 0; m < 8; m++) if (-acc[m] > best) { best = -acc[m]; bi = 8 + m; }
    g_hash[(size_t)seg * S_DIM + s] = bi;
}

// ---------------- stable counting sort (16 buckets) ----------------
__global__ void sort_kernel()
{
    const int seg = blockIdx.x;
    const int tid = threadIdx.x;
    __shared__ int tc[512][16];
    __shared__ int base[16], tot[16];

    const int* hp = g_hash + (size_t)seg * S_DIM;
#pragma unroll
    for (int m = 0; m < 16; m++) tc[tid][m] = 0;
    int myh[8];
#pragma unroll
    for (int i = 0; i < 8; i++) {
        myh[i] = hp[tid * 8 + i];
        tc[tid][myh[i]]++;
    }
    __syncthreads();
    if (tid < 16) {
        int run = 0;
        for (int t = 0; t < 512; t++) { int v = tc[t][tid]; tc[t][tid] = run; run += v; }
        tot[tid] = run;
    }
    __syncthreads();
    if (tid == 0) {
        int run = 0;
#pragma unroll
        for (int m = 0; m < 16; m++) { base[m] = run; run += tot[m]; }
    }
    __syncthreads();
#pragma unroll
    for (int i = 0; i < 8; i++) {
        int hh = myh[i];
        int pos = base[hh] + tc[tid][hh];
        tc[tid][hh]++;
        g_sidx[(size_t)seg * S_DIM + pos]  = tid * 8 + i;
        g_shash[(size_t)seg * S_DIM + pos] = hh;
    }
}

// ---------------- chunked LSH attention v2 ----------------
// one block per (seg, chunk). 256 threads. Double-buffered K/V staging
// with register-held prefetch; softmax 4 threads/row.
// reference-broadcast semantics: mask windows indexed by query SLOT.
#define QS 132
#define LGS 196
#define ATTN_SMEM ((64*QS + 2*64*QS + 64*LGS) * 4 + 2 * S_DIM * 4)

__global__ void __launch_bounds__(256) attn_kernel()
{
    extern __shared__ float sm[];
    float* q_sh = sm;                        // [64][QS]
    float* kv0  = sm + 64 * QS;              // [64][QS] buffer 0
    float* kv1  = kv0 + 64 * QS;             // [64][QS] buffer 1
    float* lg   = kv1 + 64 * QS;             // [64][LGS]
    int* sidx_sh  = (int*)(lg + 64 * LGS);   // [4096]
    int* shash_sh = sidx_sh + S_DIM;         // [4096]

    const int bid = blockIdx.x;
    const int n   = bid % NC_DIM;
    const int seg = bid / NC_DIM;            // (b*R + r)*H + h
    const int b   = seg / (R_DIM * H_DIM);
    const int h   = seg % H_DIM;
    const int tid = threadIdx.x;

    const int* gsidx  = g_sidx  + (size_t)seg * S_DIM;
    const int* gshash = g_shash + (size_t)seg * S_DIM;
    for (int i = tid; i < S_DIM; i += 256) {
        sidx_sh[i]  = gsidx[i];
        shash_sh[i] = gshash[i];
    }
    __syncthreads();

    float4 hold[8];
#define LDGC(src, kchunk)                                                      \
    {                                                                          \
        _Pragma("unroll")                                                      \
        for (int i8 = 0; i8 < 8; i8++) {                                       \
            int f = i8 * 256 + tid; int row = f >> 5; int c4 = f & 31;         \
            int tok = sidx_sh[(kchunk) * 64 + row];                            \
            hold[i8] = *(const float4*)&(src)[((size_t)tok * B_DIM + b) *      \
                                              E_DIM + h * D_DIM + c4 * 4];     \
        }                                                                      \
    }
#define STSC(dst)                                                              \
    {                                                                          \
        _Pragma("unroll")                                                      \
        for (int i8 = 0; i8 < 8; i8++) {                                       \
            int f = i8 * 256 + tid; int row = f >> 5; int c4 = f & 31;         \
            *(float4*)&(dst)[row * QS + c4 * 4] = hold[i8];                    \
        }                                                                      \
    }

    // prefetch K chunk 0 while loading q
    LDGC(g_k, (n + NC_DIM - 1) % NC_DIM);
#pragma unroll
    for (int i8 = 0; i8 < 8; i8++) {
        int f = i8 * 256 + tid; int row = f >> 5; int c4 = f & 31;
        int tok = sidx_sh[n * 64 + row];
        float4 v = *(const float4*)&g_qraw[((size_t)tok * B_DIM + b) * E_DIM +
                                           h * D_DIM + c4 * 4];
        v.x *= SCALE_F; v.y *= SCALE_F; v.z *= SCALE_F; v.w *= SCALE_F;
        *(float4*)&q_sh[row * QS + c4 * 4] = v;
    }
    STSC(kv0);
    __syncthreads();

    // ---- logits: 3 chunks of 64 keys ----
    const int tqi = tid >> 4;   // 0..15 -> queries tqi*4..+3
    const int tj  = tid & 15;   // 0..15 -> keys    tj*4..+3
    for (int c = 0; c < 3; c++) {
        if (c < 2) LDGC(g_k, (n + c + NC_DIM) % NC_DIM);
        const float* kvb = (c & 1) ? kv1 : kv0;

        float lacc[4][4];
#pragma unroll
        for (int i = 0; i < 4; i++)
#pragma unroll
            for (int j = 0; j < 4; j++) lacc[i][j] = 0.f;

        for (int d4 = 0; d4 < 32; d4++) {
            float4 qv[4], kv4[4];
#pragma unroll
            for (int i = 0; i < 4; i++)
                qv[i] = *(const float4*)&q_sh[(tqi * 4 + i) * QS + d4 * 4];
#pragma unroll
            for (int j = 0; j < 4; j++)
                kv4[j] = *(const float4*)&kvb[(tj * 4 + j) * QS + d4 * 4];
#pragma unroll
            for (int i = 0; i < 4; i++)
#pragma unroll
                for (int j = 0; j < 4; j++)
                    lacc[i][j] += qv[i].x * kv4[j].x + qv[i].y * kv4[j].y +
                                  qv[i].z * kv4[j].z + qv[i].w * kv4[j].w;
        }
#pragma unroll
        for (int i = 0; i < 4; i++) {
            int qq = tqi * 4 + i;                    // slot within chunk
            int qpos = n * 64 + qq;                  // sorted position of query
            int qhash = shash_sh[qpos];
            int qtok  = sidx_sh[qpos];
            // MASK window chunk index == slot qq (reference broadcast artifact)
            int mchunk = (qq + c + NC_DIM - 1) % NC_DIM;
#pragma unroll
            for (int j = 0; j < 4; j++) {
                int jj = tj * 4 + j;
                int mpos = mchunk * 64 + jj;
                float lv = lacc[i][j];
                if (qhash != shash_sh[mpos]) lv = NEG_F;      // different hash
                if (qtok  == sidx_sh[mpos])  lv = NEG_SELF_F; // "self"
                lg[qq * LGS + c * 64 + jj] = lv;
            }
        }
        if (c < 2) STSC((c & 1) ? kv0 : kv1);
        __syncthreads();
    }

    // prefetch V chunk 0 behind softmax
    LDGC(g_v, (n + NC_DIM - 1) % NC_DIM);

    // ---- softmax + lse: 4 threads per query row ----
    {
        const int row = tid >> 2, p = tid & 3;
        float* lrow = &lg[row * LGS];
        float m = -3.402823466e38f;
        for (int j = p; j < 192; j += 4) m = fmaxf(m, lrow[j]);
        m = fmaxf(m, __shfl_xor_sync(0xffffffffu, m, 1));
        m = fmaxf(m, __shfl_xor_sync(0xffffffffu, m, 2));
        float ssum = 0.f;
        for (int j = p; j < 192; j += 4) {
            float e = expf(lrow[j] - m);
            lrow[j] = e;
            ssum += e;
        }
        ssum += __shfl_xor_sync(0xffffffffu, ssum, 1);
        ssum += __shfl_xor_sync(0xffffffffu, ssum, 2);
        float inv = 1.0f / ssum;
        for (int j = p; j < 192; j += 4) lrow[j] *= inv;
        if (p == 0)
            g_olse[(size_t)seg * S_DIM + sidx_sh[n * 64 + row]] = m + logf(ssum);
    }
    STSC(kv0);
    __syncthreads();

    // ---- output: o = P @ V, scattered to original token order ----
    const int tq = tid >> 3;   // 0..31 -> queries tq*2, tq*2+1
    const int td = tid & 7;    // 0..7  -> dims td*16..td*16+15
    float oacc0[16], oacc1[16];
#pragma unroll
    for (int u = 0; u < 16; u++) { oacc0[u] = 0.f; oacc1[u] = 0.f; }

    for (int c = 0; c < 3; c++) {
        if (c < 2) LDGC(g_v, (n + c + NC_DIM) % NC_DIM);
        const float* kvb = (c & 1) ? kv1 : kv0;
        for (int j = 0; j < 64; j++) {
            float p0 = lg[(tq * 2 + 0) * LGS + c * 64 + j];
            float p1 = lg[(tq * 2 + 1) * LGS + c * 64 + j];
            const float* vrow = &kvb[j * QS + td * 16];
#pragma unroll
            for (int d4 = 0; d4 < 4; d4++) {
                float4 v4 = *(const float4*)&vrow[d4 * 4];
                oacc0[d4 * 4 + 0] += p0 * v4.x; oacc1[d4 * 4 + 0] += p1 * v4.x;
                oacc0[d4 * 4 + 1] += p0 * v4.y; oacc1[d4 * 4 + 1] += p1 * v4.y;
                oacc0[d4 * 4 + 2] += p0 * v4.z; oacc1[d4 * 4 + 2] += p1 * v4.z;
                oacc0[d4 * 4 + 3] += p0 * v4.w; oacc1[d4 * 4 + 3] += p1 * v4.w;
            }
        }
        if (c < 2) STSC((c & 1) ? kv0 : kv1);
        __syncthreads();
    }
#undef LDGC
#undef STSC

    {
        int tok0 = sidx_sh[n * 64 + tq * 2 + 0];
        int tok1 = sidx_sh[n * 64 + tq * 2 + 1];
        size_t base0 = ((size_t)seg * S_DIM + tok0) * D_DIM + td * 16;
        size_t base1 = ((size_t)seg * S_DIM + tok1) * D_DIM + td * 16;
#pragma unroll
        for (int d4 = 0; d4 < 4; d4++) {
            *(float4*)&g_oout[base0 + d4 * 4] =
                make_float4(oacc0[d4*4+0], oacc0[d4*4+1], oacc0[d4*4+2], oacc0[d4*4+3]);
            *(float4*)&g_oout[base1 + d4 * 4] =
                make_float4(oacc1[d4*4+0], oacc1[d4*4+1], oacc1[d4*4+2], oacc1[d4*4+3]);
        }
    }
}

// ---------------- combine rounds by softmax over lse (flat, float4) ----
__global__ void combine_kernel()
{
    const int g = blockIdx.x * 256 + threadIdx.x;     // float4 index
    const int flat = g * 4;                           // element in [S][B][E]
    const int e = flat & (E_DIM - 1);
    const int sb = flat >> 10;
    const int b = sb & 1;
    const int s = sb >> 1;
    const int h = e >> 7;
    const int d = e & 127;

    const int seg0 = (b * R_DIM + 0) * H_DIM + h;
    const int seg1 = (b * R_DIM + 1) * H_DIM + h;

    float l0 = g_olse[(size_t)seg0 * S_DIM + s];
    float l1 = g_olse[(size_t)seg1 * S_DIM + s];
    float m = fmaxf(l0, l1);
    float e0 = expf(l0 - m), e1 = expf(l1 - m);
    float inv = 1.0f / (e0 + e1);
    float w0 = e0 * inv, w1 = e1 * inv;

    float4 o0 = *(const float4*)&g_oout[((size_t)seg0 * S_DIM + s) * D_DIM + d];
    float4 o1 = *(const float4*)&g_oout[((size_t)seg1 * S_DIM + s) * D_DIM + d];
    float4 r;
    r.x = w0 * o0.x + w1 * o1.x;
    r.y = w0 * o0.y + w1 * o1.y;
    r.z = w0 * o0.z + w1 * o1.z;
    r.w = w0 * o0.w + w1 * o1.w;
    *(float4*)&g_ocomb[flat] = r;
}

// ---------------- launcher ----------------
extern "C" void kernel_launch(void* const* d_in, const int* in_sizes, int n_in,
                              void* d_out, int out_size)
{
    const float* x      = (const float*)d_in[0];
    const float* wq     = (const float*)d_in[1];
    const float* bq     = (const float*)d_in[2];
    const float* wv     = (const float*)d_in[3];
    const float* bv     = (const float*)d_in[4];
    const float* wo     = (const float*)d_in[5];
    const float* bo     = (const float*)d_in[6];
    const float* hash_w = (const float*)d_in[7];
    float* out = (float*)d_out;

    float *p_qraw, *p_v, *p_ocomb;
    cudaGetSymbolAddress((void**)&p_qraw,  g_qraw);
    cudaGetSymbolAddress((void**)&p_v,     g_v);
    cudaGetSymbolAddress((void**)&p_ocomb, g_ocomb);

    cudaFuncSetAttribute(attn_kernel, cudaFuncAttributeMaxDynamicSharedMemorySize,
                         ATTN_SMEM);

    dim3 gemm_grid(E_DIM / 128, MROWS / 128);

    gemm_bias_kernel<<<gemm_grid, 256>>>(x, wq, bq, p_qraw, MROWS, E_DIM, E_DIM);
    gemm_bias_kernel<<<gemm_grid, 256>>>(x, wv, bv, p_v,    MROWS, E_DIM, E_DIM);
    norm_kernel<<<MROWS, 256>>>();
    hash_kernel<<<dim3(S_DIM / 256, NSEG), 256>>>(hash_w);
    sort_kernel<<<NSEG, 512>>>();
    attn_kernel<<<NSEG * NC_DIM, 256, ATTN_SMEM>>>();
    combine_kernel<<<MROWS * E_DIM / 4 / 256, 256>>>();
    gemm_bias_kernel<<<gemm_grid, 256>>>(p_ocomb, wo, bo, out, MROWS, E_DIM, E_DIM);
}